// round 5
// baseline (speedup 1.0000x reference)
#include <cuda_runtime.h>

#define IMG_H 512
#define IMG_W 512
#define NIMG  16
#define TW    32
#define TH    16
#define RW    42            // TW + 10 halo
#define RH    26            // TH + 10 halo
#define RSTR  44            // raw float stride: 176B rows keep float4 alignment
#define HSTR  33            // hblur u64 stride
#define NPIX  (NIMG * IMG_H * IMG_W)
#define NBLK  (NIMG * (IMG_H / TH) * (IMG_W / TW))   // 8192

typedef unsigned long long u64;

__device__ float        g_part[NBLK];
__device__ unsigned int g_count;     // zero-init at load; reset by last block

// ---- packed f32x2 helpers (sm_100+; ptxas never emits these from C++) ----
__device__ __forceinline__ u64 pk(float lo, float hi) {
    u64 r; asm("mov.b64 %0, {%1, %2};" : "=l"(r) : "f"(lo), "f"(hi)); return r;
}
__device__ __forceinline__ void upk(float& lo, float& hi, u64 v) {
    asm("mov.b64 {%0, %1}, %2;" : "=f"(lo), "=f"(hi) : "l"(v));
}
__device__ __forceinline__ u64 fma2(u64 a, u64 b, u64 c) {
    u64 d; asm("fma.rn.f32x2 %0, %1, %2, %3;" : "=l"(d) : "l"(a), "l"(b), "l"(c)); return d;
}
__device__ __forceinline__ u64 mul2(u64 a, u64 b) {
    u64 d; asm("mul.rn.f32x2 %0, %1, %2;" : "=l"(d) : "l"(a), "l"(b)); return d;
}

__global__ void __launch_bounds__(256, 5) ssim_kernel(
    const float* __restrict__ fused,
    const float* __restrict__ imga,
    const float* __restrict__ imgb,
    float* __restrict__ out)
{
    extern __shared__ u64 smem[];
    // hblur channels (u64): [4][RH][HSTR]  = 27.5 KB
    u64* hb0 = smem;
    u64* hb1 = hb0 + RH * HSTR;
    u64* hb2 = hb1 + RH * HSTR;
    u64* hb3 = hb2 + RH * HSTR;
    // raw normalized images: [3][RH][RSTR] floats = 13.4 KB (rows 16B-aligned)
    float* sF = (float*)(hb3 + RH * HSTR);
    float* sA = sF + RH * RSTR;
    float* sB = sA + RH * RSTR;

    constexpr float GW[11] = {
        0.00102838f, 0.00759876f, 0.03600077f, 0.10936069f, 0.21300553f,
        0.26601172f,
        0.21300553f, 0.10936069f, 0.03600077f, 0.00759876f, 0.00102838f};
    const float c1 = 0.0001f;   // 0.01^2
    const float c2 = 0.0009f;   // 0.03^2

    const int tid = threadIdx.x;
    const int gx0 = blockIdx.x * TW - 5;
    const int gy0 = blockIdx.y * TH - 5;
    const size_t base = (size_t)blockIdx.z * (IMG_H * IMG_W);
    const float* fP = fused + base;
    const float* aP = imga + base;
    const float* bP = imgb + base;

    // ---- Stage 0: load halo, normalize (x+1)/2, store raw channels ----
    for (int i = tid; i < RH * RW; i += 256) {
        int y = i / RW;
        int x = i - y * RW;
        int gy = gy0 + y, gx = gx0 + x;
        float f = 0.f, a = 0.f, b = 0.f;
        if (gy >= 0 && gy < IMG_H && gx >= 0 && gx < IMG_W) {
            int g = gy * IMG_W + gx;
            f = fP[g] * 0.5f + 0.5f;
            a = aP[g] * 0.5f + 0.5f;
            b = bP[g] * 0.5f + 0.5f;
        }
        int o = y * RSTR + x;
        sF[o] = f;
        sA[o] = a;
        sB[o] = b;
    }
    __syncthreads();

    // ---- Stage 1: horizontal blur, 4 outputs/thread, single balanced pass.
    // 26 rows x 8 groups = 208 tasks on 256 threads. Window reads via LDS.128,
    // products formed in registers, packed fma2 accumulation.
    if (tid < RH * 8) {
        u64 W2[11];
#pragma unroll
        for (int k = 0; k < 11; k++) W2[k] = pk(GW[k], GW[k]);

        const int y  = tid >> 3;
        const int x0 = (tid & 7) * 4;           // outputs x0..x0+3
        const float4* f4 = (const float4*)(sF + y * RSTR + x0);
        const float4* a4 = (const float4*)(sA + y * RSTR + x0);
        const float4* b4 = (const float4*)(sB + y * RSTR + x0);

        u64 acc[4][4];
#pragma unroll
        for (int j = 0; j < 4; j++)
#pragma unroll
            for (int c = 0; c < 4; c++) acc[j][c] = 0ull;

#pragma unroll
        for (int q = 0; q < 4; q++) {           // 4 float4 chunks = 16 pixels
            float4 fv = f4[q], av = a4[q], bv = b4[q];
            float fs[4] = {fv.x, fv.y, fv.z, fv.w};
            float as[4] = {av.x, av.y, av.z, av.w};
            float bs[4] = {bv.x, bv.y, bv.z, bv.w};
#pragma unroll
            for (int m = 0; m < 4; m++) {
                int k = q * 4 + m;
                if (k >= 14) continue;          // only 14 window pixels used
                float f = fs[m], a = as[m], b = bs[m];
                u64 ab = pk(a, b);
                u64 P0 = pk(f, a);              // (f , a )
                u64 P1 = pk(b, f * f);          // (b , f2)
                u64 P2 = mul2(ab, ab);          // (a2, b2)
                u64 P3 = mul2(pk(f, f), ab);    // (fa, fb)
#pragma unroll
                for (int j = 0; j < 4; j++) {
                    int t = k - j;              // compile-time per (k,j)
                    if (t >= 0 && t < 11) {
                        acc[j][0] = fma2(P0, W2[t], acc[j][0]);
                        acc[j][1] = fma2(P1, W2[t], acc[j][1]);
                        acc[j][2] = fma2(P2, W2[t], acc[j][2]);
                        acc[j][3] = fma2(P3, W2[t], acc[j][3]);
                    }
                }
            }
        }
#pragma unroll
        for (int j = 0; j < 4; j++) {
            int o = y * HSTR + x0 + j;
            hb0[o] = acc[j][0];
            hb1[o] = acc[j][1];
            hb2[o] = acc[j][2];
            hb3[o] = acc[j][3];
        }
    }
    __syncthreads();

    // ---- Stage 2: vertical blur (2 outputs/thread) + SSIM ----
    float lsum = 0.f;
    {
        u64 W2[11];
#pragma unroll
        for (int k = 0; k < 11; k++) W2[k] = pk(GW[k], GW[k]);

        const int x = tid & 31;
        const int ybase = (tid >> 5) * 2;       // 8 warps x 2 rows = 16 rows

        u64 acc[2][4];
#pragma unroll
        for (int j = 0; j < 2; j++)
#pragma unroll
            for (int c = 0; c < 4; c++) acc[j][c] = 0ull;

#pragma unroll
        for (int r = 0; r < 12; r++) {
            int o = (ybase + r) * HSTR + x;
            u64 q0 = hb0[o], q1 = hb1[o], q2 = hb2[o], q3 = hb3[o];
#pragma unroll
            for (int j = 0; j < 2; j++) {
                int t = r - j;
                if (t >= 0 && t < 11) {
                    acc[j][0] = fma2(q0, W2[t], acc[j][0]);
                    acc[j][1] = fma2(q1, W2[t], acc[j][1]);
                    acc[j][2] = fma2(q2, W2[t], acc[j][2]);
                    acc[j][3] = fma2(q3, W2[t], acc[j][3]);
                }
            }
        }

#pragma unroll
        for (int j = 0; j < 2; j++) {
            float muF, muA, muB, eF2, eA2, eB2, eFA, eFB;
            upk(muF, muA, acc[j][0]);
            upk(muB, eF2, acc[j][1]);
            upk(eA2, eB2, acc[j][2]);
            upk(eFA, eFB, acc[j][3]);
            float muF2 = muF * muF;
            float sF2  = eF2 - muF2;
            // pair (fused, img_a)
            float muA2 = muA * muA;
            float m12a = muF * muA;
            float sA2  = eA2 - muA2;
            float s12a = eFA - m12a;
            float na   = (2.f * m12a + c1) * (2.f * s12a + c2);
            float da   = (muF2 + muA2 + c1) * (sF2 + sA2 + c2);
            // pair (fused, img_b)
            float muB2 = muB * muB;
            float m12b = muF * muB;
            float sB2  = eB2 - muB2;
            float s12b = eFB - m12b;
            float nb   = (2.f * m12b + c1) * (2.f * s12b + c2);
            float db   = (muF2 + muB2 + c1) * (sF2 + sB2 + c2);
            // combined: na/da + nb/db, one division
            float num = fmaf(na, db, nb * da);
            lsum += __fdividef(num, da * db);
        }
    }

    // ---- Block reduction -> deterministic per-block partial ----
#pragma unroll
    for (int o = 16; o > 0; o >>= 1)
        lsum += __shfl_down_sync(0xffffffffu, lsum, o);

    __shared__ float wsum[8];
    __shared__ bool  is_last;
    if ((tid & 31) == 0) wsum[tid >> 5] = lsum;
    __syncthreads();
    if (tid == 0) {
        float v = 0.f;
#pragma unroll
        for (int w = 0; w < 8; w++) v += wsum[w];
        int bi = ((int)blockIdx.z * gridDim.y + blockIdx.y) * gridDim.x
                 + blockIdx.x;
        g_part[bi] = v;
        __threadfence();
        unsigned prev = atomicAdd(&g_count, 1u);
        is_last = (prev == NBLK - 1);
    }
    __syncthreads();

    // ---- Last block: reduce all partials, write output, reset counter ----
    if (is_last) {
        double s = 0.0;
        for (int i = tid; i < NBLK; i += 256) s += (double)g_part[i];
#pragma unroll
        for (int o = 16; o > 0; o >>= 1)
            s += __shfl_down_sync(0xffffffffu, s, o);
        __shared__ double dsum[8];
        if ((tid & 31) == 0) dsum[tid >> 5] = s;
        __syncthreads();
        if (tid == 0) {
            double tot = 0.0;
#pragma unroll
            for (int w = 0; w < 8; w++) tot += dsum[w];
            out[0] = (float)(1.0 - tot / (2.0 * (double)NPIX));
            g_count = 0;      // reset for next graph replay
        }
    }
}

extern "C" void kernel_launch(void* const* d_in, const int* in_sizes, int n_in,
                              void* d_out, int out_size)
{
    (void)in_sizes; (void)n_in; (void)out_size;
    const float* fused = (const float*)d_in[0];
    const float* imga  = (const float*)d_in[1];
    const float* imgb  = (const float*)d_in[2];

    const size_t smem_bytes = (size_t)(4 * RH * HSTR) * sizeof(u64)
                            + (size_t)(3 * RH * RSTR) * sizeof(float); // ~41 KB
    cudaFuncSetAttribute(ssim_kernel,
                         cudaFuncAttributeMaxDynamicSharedMemorySize,
                         (int)smem_bytes);

    dim3 grid(IMG_W / TW, IMG_H / TH, NIMG);
    ssim_kernel<<<grid, 256, smem_bytes>>>(fused, imga, imgb, (float*)d_out);
}

// round 6
// speedup vs baseline: 1.4994x; 1.4994x over previous
#include <cuda_runtime.h>

#define IMG_H 512
#define IMG_W 512
#define NIMG  16
#define TW    32
#define TH    32
#define RH    42            // TH + 10 halo rows of hblur
#define HSTR  34            // hblur u64 stride (even -> 16B-aligned px pairs)
#define NPIX  (NIMG * IMG_H * IMG_W)
#define NBLK  (NIMG * (IMG_H / TH) * (IMG_W / TW))   // 4096

typedef unsigned long long u64;

__device__ float        g_part[NBLK];
__device__ unsigned int g_count;     // zero-init at load; reset by last block

// ---- packed f32x2 helpers (sm_100+; ptxas never emits these from C++) ----
__device__ __forceinline__ u64 pk(float lo, float hi) {
    u64 r; asm("mov.b64 %0, {%1, %2};" : "=l"(r) : "f"(lo), "f"(hi)); return r;
}
__device__ __forceinline__ void upk(float& lo, float& hi, u64 v) {
    asm("mov.b64 {%0, %1}, %2;" : "=f"(lo), "=f"(hi) : "l"(v));
}
__device__ __forceinline__ u64 fma2(u64 a, u64 b, u64 c) {
    u64 d; asm("fma.rn.f32x2 %0, %1, %2, %3;" : "=l"(d) : "l"(a), "l"(b), "l"(c)); return d;
}

__global__ void __launch_bounds__(256, 4) ssim_kernel(
    const float* __restrict__ fused,
    const float* __restrict__ imga,
    const float* __restrict__ imgb,
    float* __restrict__ out)
{
    extern __shared__ u64 smem[];
    u64* hb0 = smem;                       // [RH][HSTR] packed (muF, muA)
    u64* hb1 = hb0 + RH * HSTR;            // (muB, eF2)
    u64* hb2 = hb1 + RH * HSTR;            // (eA2, eB2)
    u64* hb3 = hb2 + RH * HSTR;            // (eFA, eFB)

    constexpr float GW[11] = {
        0.00102838f, 0.00759876f, 0.03600077f, 0.10936069f, 0.21300553f,
        0.26601172f,
        0.21300553f, 0.10936069f, 0.03600077f, 0.00759876f, 0.00102838f};
    const float c1 = 0.0001f;
    const float c2 = 0.0009f;

    const int tid = threadIdx.x;
    const int bx  = blockIdx.x;
    const int gy0 = blockIdx.y * TH - 5;
    const size_t base = (size_t)blockIdx.z * (IMG_H * IMG_W);
    const float* fP = fused + base;
    const float* aP = imga + base;
    const float* bP = imgb + base;
    const bool edge_x = (bx == 0) | (bx == (IMG_W / TW) - 1);

    // ---- Stage 1: horizontal blur straight from gmem, 4 outputs/task ----
    for (int t = tid; t < RH * 8; t += 256) {
        const int y  = t >> 3;
        const int x0 = (t & 7) * 4;
        const int gy = gy0 + y;

        float acc[4][8];
#pragma unroll
        for (int j = 0; j < 4; j++)
#pragma unroll
            for (int c = 0; c < 8; c++) acc[j][c] = 0.f;

        if (gy >= 0 && gy < IMG_H) {
            if (!edge_x) {
                const int gxa = bx * TW + x0 - 8;       // multiple of 4, >=24
                const float4* f4 = (const float4*)(fP + gy * IMG_W + gxa);
                const float4* a4 = (const float4*)(aP + gy * IMG_W + gxa);
                const float4* b4 = (const float4*)(bP + gy * IMG_W + gxa);
#pragma unroll
                for (int q = 0; q < 5; q++) {
                    float4 fv = f4[q], av = a4[q], bv = b4[q];
                    float fs[4] = {fv.x, fv.y, fv.z, fv.w};
                    float as[4] = {av.x, av.y, av.z, av.w};
                    float bs[4] = {bv.x, bv.y, bv.z, bv.w};
#pragma unroll
                    for (int m = 0; m < 4; m++) {
                        int k = q * 4 + m - 3;          // window px 0..13
                        if (k < 0 || k >= 14) continue;
                        float f = fs[m] * 0.5f + 0.5f;
                        float a = as[m] * 0.5f + 0.5f;
                        float b = bs[m] * 0.5f + 0.5f;
                        float v[8] = {f, a, b, f * f, a * a, b * b,
                                      f * a, f * b};
#pragma unroll
                        for (int j = 0; j < 4; j++) {
                            int tt = k - j;
                            if (tt >= 0 && tt < 11) {
#pragma unroll
                                for (int c = 0; c < 8; c++)
                                    acc[j][c] = fmaf(v[c], GW[tt], acc[j][c]);
                            }
                        }
                    }
                }
            } else {
                const int gxw = bx * TW + x0 - 5;
                const float* frow = fP + gy * IMG_W;
                const float* arow = aP + gy * IMG_W;
                const float* brow = bP + gy * IMG_W;
#pragma unroll
                for (int k = 0; k < 14; k++) {
                    int gx = gxw + k;
                    float f = 0.f, a = 0.f, b = 0.f;
                    if (gx >= 0 && gx < IMG_W) {
                        f = frow[gx] * 0.5f + 0.5f;
                        a = arow[gx] * 0.5f + 0.5f;
                        b = brow[gx] * 0.5f + 0.5f;
                    }
                    float v[8] = {f, a, b, f * f, a * a, b * b, f * a, f * b};
#pragma unroll
                    for (int j = 0; j < 4; j++) {
                        int tt = k - j;
                        if (tt >= 0 && tt < 11) {
#pragma unroll
                            for (int c = 0; c < 8; c++)
                                acc[j][c] = fmaf(v[c], GW[tt], acc[j][c]);
                        }
                    }
                }
            }
        }

        const int o = y * HSTR + x0;        // even -> 16B aligned
        ((ulonglong2*)(hb0 + o))[0] = make_ulonglong2(pk(acc[0][0], acc[0][1]), pk(acc[1][0], acc[1][1]));
        ((ulonglong2*)(hb0 + o))[1] = make_ulonglong2(pk(acc[2][0], acc[2][1]), pk(acc[3][0], acc[3][1]));
        ((ulonglong2*)(hb1 + o))[0] = make_ulonglong2(pk(acc[0][2], acc[0][3]), pk(acc[1][2], acc[1][3]));
        ((ulonglong2*)(hb1 + o))[1] = make_ulonglong2(pk(acc[2][2], acc[2][3]), pk(acc[3][2], acc[3][3]));
        ((ulonglong2*)(hb2 + o))[0] = make_ulonglong2(pk(acc[0][4], acc[0][5]), pk(acc[1][4], acc[1][5]));
        ((ulonglong2*)(hb2 + o))[1] = make_ulonglong2(pk(acc[2][4], acc[2][5]), pk(acc[3][4], acc[3][5]));
        ((ulonglong2*)(hb3 + o))[0] = make_ulonglong2(pk(acc[0][6], acc[0][7]), pk(acc[1][6], acc[1][7]));
        ((ulonglong2*)(hb3 + o))[1] = make_ulonglong2(pk(acc[2][6], acc[2][7]), pk(acc[3][6], acc[3][7]));
    }
    __syncthreads();

    // ---- Stage 2: vertical blur (4 outputs/thread) + SSIM ----
    float lsum = 0.f;
    {
        const int x  = tid & 31;
        const int yb = (tid >> 5) * 4;

        u64 acc[4][4];
#pragma unroll
        for (int j = 0; j < 4; j++)
#pragma unroll
            for (int c = 0; c < 4; c++) acc[j][c] = 0ull;

#pragma unroll
        for (int r = 0; r < 14; r++) {
            int o = (yb + r) * HSTR + x;
            u64 q0 = hb0[o], q1 = hb1[o], q2 = hb2[o], q3 = hb3[o];
#pragma unroll
            for (int j = 0; j < 4; j++) {
                int tt = r - j;
                if (tt >= 0 && tt < 11) {
                    u64 w = pk(GW[tt], GW[tt]);     // imm pair, remat-friendly
                    acc[j][0] = fma2(q0, w, acc[j][0]);
                    acc[j][1] = fma2(q1, w, acc[j][1]);
                    acc[j][2] = fma2(q2, w, acc[j][2]);
                    acc[j][3] = fma2(q3, w, acc[j][3]);
                }
            }
        }

#pragma unroll
        for (int j = 0; j < 4; j++) {
            float muF, muA, muB, eF2, eA2, eB2, eFA, eFB;
            upk(muF, muA, acc[j][0]);
            upk(muB, eF2, acc[j][1]);
            upk(eA2, eB2, acc[j][2]);
            upk(eFA, eFB, acc[j][3]);
            float muF2 = muF * muF;
            float sF2  = eF2 - muF2;
            float muA2 = muA * muA;
            float m12a = muF * muA;
            float sA2  = eA2 - muA2;
            float s12a = eFA - m12a;
            float na   = (2.f * m12a + c1) * (2.f * s12a + c2);
            float da   = (muF2 + muA2 + c1) * (sF2 + sA2 + c2);
            float muB2 = muB * muB;
            float m12b = muF * muB;
            float sB2  = eB2 - muB2;
            float s12b = eFB - m12b;
            float nb   = (2.f * m12b + c1) * (2.f * s12b + c2);
            float db   = (muF2 + muB2 + c1) * (sF2 + sB2 + c2);
            float num = fmaf(na, db, nb * da);
            lsum += __fdividef(num, da * db);
        }
    }

    // ---- Block reduction -> deterministic per-block partial ----
#pragma unroll
    for (int o = 16; o > 0; o >>= 1)
        lsum += __shfl_down_sync(0xffffffffu, lsum, o);

    __shared__ float wsum[8];
    __shared__ bool  is_last;
    if ((tid & 31) == 0) wsum[tid >> 5] = lsum;
    __syncthreads();
    if (tid == 0) {
        float v = 0.f;
#pragma unroll
        for (int w = 0; w < 8; w++) v += wsum[w];
        int bi = ((int)blockIdx.z * gridDim.y + blockIdx.y) * gridDim.x
                 + blockIdx.x;
        g_part[bi] = v;
        __threadfence();
        unsigned prev = atomicAdd(&g_count, 1u);
        is_last = (prev == NBLK - 1);
    }
    __syncthreads();

    if (is_last) {
        double s = 0.0;
        for (int i = tid; i < NBLK; i += 256) s += (double)g_part[i];
#pragma unroll
        for (int o = 16; o > 0; o >>= 1)
            s += __shfl_down_sync(0xffffffffu, s, o);
        __shared__ double dsum[8];
        if ((tid & 31) == 0) dsum[tid >> 5] = s;
        __syncthreads();
        if (tid == 0) {
            double tot = 0.0;
#pragma unroll
            for (int w = 0; w < 8; w++) tot += dsum[w];
            out[0] = (float)(1.0 - tot / (2.0 * (double)NPIX));
            g_count = 0;      // reset for next graph replay
        }
    }
}

extern "C" void kernel_launch(void* const* d_in, const int* in_sizes, int n_in,
                              void* d_out, int out_size)
{
    (void)in_sizes; (void)n_in; (void)out_size;
    const float* fused = (const float*)d_in[0];
    const float* imga  = (const float*)d_in[1];
    const float* imgb  = (const float*)d_in[2];

    const size_t smem_bytes = (size_t)(4 * RH * HSTR) * sizeof(u64); // 45.7 KB
    cudaFuncSetAttribute(ssim_kernel,
                         cudaFuncAttributeMaxDynamicSharedMemorySize,
                         (int)smem_bytes);

    dim3 grid(IMG_W / TW, IMG_H / TH, NIMG);
    ssim_kernel<<<grid, 256, smem_bytes>>>(fused, imga, imgb, (float*)d_out);
}